// round 7
// baseline (speedup 1.0000x reference)
#include <cuda_runtime.h>
#include <cuda_bf16.h>
#include <math.h>
#include <stdint.h>

// Problem dims (fixed by dataset)
#define T_STEPS 2048
#define BATCH   256
#define INP     256
#define HID     512
#define KTOT    768            // concat K: [x_t | h]

// Partition: block = (jTile, bTile): 16 hidden cols x 64 batch rows
#define JT 16                  // hidden columns per block
#define BT 64                  // batch rows per block
#define NROWS 64               // gate rows per block = 4 gates * JT
#define KC 32                  // K chunk staged per iteration
#define NCH (KTOT / KC)        // 24 chunks
#define NBLK 128               // 32 x 4 grid, all co-resident (<=148 SMs)

// SMEM strides (in 32-bit words), padded for conflict-free fragment loads
#define W_STRIDE 388           // 384 words (768 bf16) + 4 pad  -> stride%32==4
#define A_STRIDE 20            // 16 words (32 bf16)  + 4 pad  -> stride%32==20
#define G_STRIDE 65            // gates buffer row stride (floats)

// SMEM layout (bytes)
#define SZ_W      (NROWS * W_STRIDE * 4)            // 99,328
#define OFF_WHI   0
#define OFF_WLO   (OFF_WHI + SZ_W)                  // 99,328
#define OFF_ABUF  (OFF_WLO + SZ_W)                  // 198,656
#define SZ_ABUF   (2 * 2 * BT * A_STRIDE * 4)       // 20,480 (dbuf x hi/lo x 64 x 20)
#define OFF_GATES OFF_ABUF                          // overlay (64*65*4 = 16,640 <= 20,480)
#define OFF_BIAS  (OFF_ABUF + SZ_ABUF)              // 219,136
#define OFF_SENSE (OFF_BIAS + NROWS * 4)            // 219,392
#define SMEM_BYTES (OFF_SENSE + 16)                 // 219,408

// Persistent state (device globals: allocation-free scratch)
__device__ float g_h0[BATCH * HID];
__device__ float g_h1[BATCH * HID];
__device__ float g_c [BATCH * HID];
__device__ volatile int g_sense;   // zero-init
__device__ int          g_count;   // zero-init

__global__ void init_state_kernel(const float* __restrict__ h0,
                                  const float* __restrict__ c0) {
    int i = blockIdx.x * blockDim.x + threadIdx.x;
    if (i < BATCH * HID) { g_h0[i] = h0[i]; g_c[i] = c0[i]; }
}

__device__ __forceinline__ uint32_t b2u(__nv_bfloat162 v) {
    return *reinterpret_cast<uint32_t*>(&v);
}

// split fp32 pair -> (hi bf16x2 word, lo bf16x2 word); low 16 bits = first (even-k) element
__device__ __forceinline__ void split2(float2 v, uint32_t& wh, uint32_t& wl) {
    __nv_bfloat162 hi2 = __floats2bfloat162_rn(v.x, v.y);
    float lx = v.x - __bfloat162float(__low2bfloat16(hi2));
    float ly = v.y - __bfloat162float(__high2bfloat16(hi2));
    __nv_bfloat162 lo2 = __floats2bfloat162_rn(lx, ly);
    wh = b2u(hi2); wl = b2u(lo2);
}

#define MMA_BF16(D, A, B0, B1)                                              \
    asm volatile("mma.sync.aligned.m16n8k16.row.col.f32.bf16.bf16.f32 "     \
                 "{%0,%1,%2,%3}, {%4,%5,%6,%7}, {%8,%9}, {%0,%1,%2,%3};"    \
                 : "+f"((D)[0]), "+f"((D)[1]), "+f"((D)[2]), "+f"((D)[3])   \
                 : "r"((A)[0]), "r"((A)[1]), "r"((A)[2]), "r"((A)[3]),      \
                   "r"(B0), "r"(B1));

// Persistent fused LSTM: tensor-core GEMM (bf16x3 ~ fp32), SMEM-resident weights,
// grid barrier between timesteps. Grid (32, 4) x 256 threads.
__global__ __launch_bounds__(256, 1)
void lstm_tc_kernel(const float* __restrict__ x_all,  // [T, BATCH, INP]
                    const float* __restrict__ W_ih,   // [4*HID, INP]
                    const float* __restrict__ W_hh,   // [4*HID, HID]
                    const float* __restrict__ b_ih,   // [4*HID]
                    const float* __restrict__ b_hh)   // [4*HID]
{
    extern __shared__ char sm[];
    uint32_t* Whi    = (uint32_t*)(sm + OFF_WHI);
    uint32_t* Wlo    = (uint32_t*)(sm + OFF_WLO);
    uint32_t* Ab     = (uint32_t*)(sm + OFF_ABUF);   // [(buf*2+hl)*BT + row]*A_STRIDE + col
    float*    gates  = (float*)   (sm + OFF_GATES);  // overlay on Ab
    float*    bias_s = (float*)   (sm + OFF_BIAS);
    int*      s_ls   = (int*)     (sm + OFF_SENSE);

    const int tid  = threadIdx.x;
    const int lane = tid & 31, warp = tid >> 5;
    const int wm = warp & 1;        // batch-half of the 64x64 tile
    const int wn = warp >> 1;       // 0..3: 16-gatecol slice
    const int lq  = lane >> 2;      // 0..7
    const int lr4 = lane & 3;       // 0..3
    const int jTile = blockIdx.x;   // 0..31
    const int bTile = blockIdx.y;   // 0..3

    // ---- one-time: load + split weights into SMEM (rows r = tt*16 + jj) ----
    {
        int r  = tid >> 2;                        // 0..63
        int grow = (r >> 4) * HID + jTile * JT + (r & 15);
        int kbase = (tid & 3) * 192;
        for (int i = 0; i < 96; ++i) {
            int k = kbase + 2 * i;
            float2 v = (k < INP)
                ? *(const float2*)(W_ih + (size_t)grow * INP + k)
                : *(const float2*)(W_hh + (size_t)grow * HID + (k - INP));
            uint32_t wh, wl; split2(v, wh, wl);
            Whi[r * W_STRIDE + k / 2] = wh;
            Wlo[r * W_STRIDE + k / 2] = wl;
        }
        if (tid < NROWS) {
            int gr = (tid >> 4) * HID + jTile * JT + (tid & 15);
            bias_s[tid] = b_ih[gr] + b_hh[gr];
        }
        if (tid == 0) *s_ls = g_sense;
    }
    __syncthreads();

    // staging assignment: 4 threads per batch row, 8 k-floats each
    const int srow  = tid >> 2;            // 0..63
    const int skoff = (tid & 3) * 8;       // k offset within chunk
    const int brow  = bTile * BT + srow;   // global batch row
    const int swc   = (tid & 3) * 4;       // word col base in A buf

    for (int t = 0; t < T_STEPS; ++t) {
        const float* __restrict__ x_t   = x_all + (size_t)t * BATCH * INP;
        const float* __restrict__ h_in  = (t & 1) ? g_h1 : g_h0;
        float*       __restrict__ h_out = (t & 1) ? g_h0 : g_h1;

        float d[2][2][4];
#pragma unroll
        for (int mf = 0; mf < 2; ++mf)
#pragma unroll
            for (int nf = 0; nf < 2; ++nf)
#pragma unroll
                for (int q = 0; q < 4; ++q) d[mf][nf][q] = 0.f;

        // ---- stage chunk 0 (pure x) into buffer 0 ----
        float2 pf[4];
        {
            const float* src = x_t + (size_t)brow * INP + skoff;
#pragma unroll
            for (int i = 0; i < 4; ++i) pf[i] = *(const float2*)(src + 2 * i);
#pragma unroll
            for (int i = 0; i < 4; ++i) {
                uint32_t wh, wl; split2(pf[i], wh, wl);
                Ab[(0) * BT * A_STRIDE + srow * A_STRIDE + swc + i] = wh;
                Ab[(1) * BT * A_STRIDE + srow * A_STRIDE + swc + i] = wl;
            }
        }
        __syncthreads();

        int buf = 0;
        for (int c = 0; c < NCH; ++c) {
            // prefetch next chunk into registers
            if (c < NCH - 1) {
                int kg = (c + 1) * KC + skoff;
                const float* src = (kg < INP)
                    ? (x_t  + (size_t)brow * INP + kg)
                    : (h_in + (size_t)brow * HID + (kg - INP));
#pragma unroll
                for (int i = 0; i < 4; ++i) pf[i] = *(const float2*)(src + 2 * i);
            }

            // MMA over the 2 k-steps (16 each) of this chunk
            const int base_h = (buf * 2 + 0) * BT * A_STRIDE;
            const int base_l = (buf * 2 + 1) * BT * A_STRIDE;
#pragma unroll
            for (int ks = 0; ks < 2; ++ks) {
                const int gw  = c * 16 + ks * 8 + lr4;   // weight word col
                uint32_t bh[2][2], bl[2][2];
#pragma unroll
                for (int nf = 0; nf < 2; ++nf) {
                    int r = wn * 16 + nf * 8 + lq;
                    bh[nf][0] = Whi[r * W_STRIDE + gw];
                    bh[nf][1] = Whi[r * W_STRIDE + gw + 4];
                    bl[nf][0] = Wlo[r * W_STRIDE + gw];
                    bl[nf][1] = Wlo[r * W_STRIDE + gw + 4];
                }
                const int wc0 = ks * 8 + lr4;
#pragma unroll
                for (int mf = 0; mf < 2; ++mf) {
                    int m0 = wm * 32 + mf * 16 + lq;
                    uint32_t ah[4], al[4];
                    ah[0] = Ab[base_h +  m0      * A_STRIDE + wc0];
                    ah[1] = Ab[base_h + (m0 + 8) * A_STRIDE + wc0];
                    ah[2] = Ab[base_h +  m0      * A_STRIDE + wc0 + 4];
                    ah[3] = Ab[base_h + (m0 + 8) * A_STRIDE + wc0 + 4];
                    al[0] = Ab[base_l +  m0      * A_STRIDE + wc0];
                    al[1] = Ab[base_l + (m0 + 8) * A_STRIDE + wc0];
                    al[2] = Ab[base_l +  m0      * A_STRIDE + wc0 + 4];
                    al[3] = Ab[base_l + (m0 + 8) * A_STRIDE + wc0 + 4];
#pragma unroll
                    for (int nf = 0; nf < 2; ++nf) {
                        MMA_BF16(d[mf][nf], ah, bh[nf][0], bh[nf][1]);  // hi*hi
                        MMA_BF16(d[mf][nf], ah, bl[nf][0], bl[nf][1]);  // hi*lo
                        MMA_BF16(d[mf][nf], al, bh[nf][0], bh[nf][1]);  // lo*hi
                    }
                }
            }

            // commit prefetched chunk into the other buffer
            if (c < NCH - 1) {
                int nbuf = buf ^ 1;
#pragma unroll
                for (int i = 0; i < 4; ++i) {
                    uint32_t wh, wl; split2(pf[i], wh, wl);
                    Ab[(nbuf * 2 + 0) * BT * A_STRIDE + srow * A_STRIDE + swc + i] = wh;
                    Ab[(nbuf * 2 + 1) * BT * A_STRIDE + srow * A_STRIDE + swc + i] = wl;
                }
            }
            __syncthreads();
            buf ^= 1;
        }

        // ---- spill accumulators to SMEM gates buffer (overlays A bufs) ----
#pragma unroll
        for (int mf = 0; mf < 2; ++mf)
#pragma unroll
            for (int nf = 0; nf < 2; ++nf) {
                int m = wm * 32 + mf * 16 + lq;
                int n = wn * 16 + nf * 8 + lr4 * 2;
                gates[ m      * G_STRIDE + n    ] = d[mf][nf][0];
                gates[ m      * G_STRIDE + n + 1] = d[mf][nf][1];
                gates[(m + 8) * G_STRIDE + n    ] = d[mf][nf][2];
                gates[(m + 8) * G_STRIDE + n + 1] = d[mf][nf][3];
            }
        __syncthreads();

        // ---- fused LSTM epilogue: thread owns 4 (b, j) cells ----
        {
            int b  = tid >> 2;
            int bg = bTile * BT + b;
#pragma unroll
            for (int i = 0; i < 4; ++i) {
                int j  = (tid & 3) * 4 + i;
                float gi = gates[b * G_STRIDE + j]      + bias_s[j];
                float gf = gates[b * G_STRIDE + 16 + j] + bias_s[16 + j];
                float gg = gates[b * G_STRIDE + 32 + j] + bias_s[32 + j];
                float go = gates[b * G_STRIDE + 48 + j] + bias_s[48 + j];
                float iv = 1.f / (1.f + expf(-gi));
                float fv = 1.f / (1.f + expf(-gf));
                float gv = tanhf(gg);
                float ov = 1.f / (1.f + expf(-go));
                int   jg = jTile * JT + j;
                size_t idx = (size_t)bg * HID + jg;
                float cn = fv * g_c[idx] + iv * gv;
                g_c[idx]   = cn;
                h_out[idx] = ov * tanhf(cn);
            }
        }

        // ---- grid barrier (sense-reversing): publish h_out to all blocks ----
        __syncthreads();
        if (tid == 0) {
            int ls = *s_ls ^ 1;
            *s_ls = ls;
            __threadfence();
            if (atomicAdd(&g_count, 1) == NBLK - 1) {
                g_count = 0;
                __threadfence();
                g_sense = ls;
            } else {
                while (g_sense != ls) { }
                __threadfence();
            }
        }
        __syncthreads();
    }
}

// out[b] = h_last[b] . W_dec + b_dec   (h_last lives in g_h0 after 2048 steps)
__global__ void decode_kernel(const float* __restrict__ W_dec,
                              const float* __restrict__ b_dec,
                              float* __restrict__ out)
{
    int b = blockIdx.x;
    float s = 0.f;
    for (int k = threadIdx.x; k < HID; k += 128)
        s += g_h0[(size_t)b * HID + k] * W_dec[k];
    __shared__ float red[128];
    red[threadIdx.x] = s;
    __syncthreads();
#pragma unroll
    for (int off = 64; off > 0; off >>= 1) {
        if (threadIdx.x < off) red[threadIdx.x] += red[threadIdx.x + off];
        __syncthreads();
    }
    if (threadIdx.x == 0) out[b] = red[0] + b_dec[0];
}

extern "C" void kernel_launch(void* const* d_in, const int* in_sizes, int n_in,
                              void* d_out, int out_size)
{
    (void)in_sizes; (void)n_in; (void)out_size;
    const float* x     = (const float*)d_in[0];  // [T, B, I]
    const float* h0    = (const float*)d_in[1];  // [B, H]
    const float* c0    = (const float*)d_in[2];  // [B, H]
    const float* W_ih  = (const float*)d_in[3];  // [4H, I]
    const float* W_hh  = (const float*)d_in[4];  // [4H, H]
    const float* b_ih  = (const float*)d_in[5];  // [4H]
    const float* b_hh  = (const float*)d_in[6];  // [4H]
    const float* W_dec = (const float*)d_in[7];  // [1, H]
    const float* b_dec = (const float*)d_in[8];  // [1]
    float* out = (float*)d_out;                  // [B, 1]

    static bool attr_set = false;
    if (!attr_set) {
        cudaFuncSetAttribute(lstm_tc_kernel,
                             cudaFuncAttributeMaxDynamicSharedMemorySize, SMEM_BYTES);
        attr_set = true;
    }

    init_state_kernel<<<(BATCH * HID + 255) / 256, 256>>>(h0, c0);

    dim3 grid(HID / JT, BATCH / BT);   // (32, 4) = 128 blocks, all co-resident
    lstm_tc_kernel<<<grid, 256, SMEM_BYTES>>>(x, W_ih, W_hh, b_ih, b_hh);

    decode_kernel<<<BATCH, 128>>>(W_dec, b_dec, out);
}

// round 8
// speedup vs baseline: 1.0151x; 1.0151x over previous
#include <cuda_runtime.h>
#include <cuda_bf16.h>
#include <math.h>
#include <stdint.h>

// Problem dims (fixed by dataset)
#define T_STEPS 2048
#define BATCH   256
#define INP     256
#define HID     512
#define KTOT    768            // concat K: [x_t | h]

// Partition: block = (jTile, bTile): 16 hidden cols x 64 batch rows
#define JT 16                  // hidden columns per block
#define BT 64                  // batch rows per block
#define NROWS 64               // gate rows per block = 4 gates * JT
#define KC 32                  // K chunk staged per iteration
#define NCH (KTOT / KC)        // 24 chunks
#define NBLK 128               // 32 x 4 grid, all co-resident (<=148 SMs)

// SMEM strides (in 32-bit words), padded for conflict-free fragment loads
#define W_STRIDE 388           // 384 words (768 bf16) + 4 pad  -> stride%32==4
#define A_STRIDE 20            // 16 words (32 bf16)  + 4 pad  -> stride%32==20
#define G_STRIDE 65            // gates buffer row stride (floats)

// SMEM layout (bytes)
#define SZ_W      (NROWS * W_STRIDE * 4)            // 99,328
#define OFF_WHI   0
#define OFF_WLO   (OFF_WHI + SZ_W)                  // 99,328
#define OFF_ABUF  (OFF_WLO + SZ_W)                  // 198,656
#define SZ_ABUF   (2 * 2 * BT * A_STRIDE * 4)       // 20,480 (dbuf x hi/lo x 64 x 20)
#define OFF_GATES OFF_ABUF                          // overlay (64*65*4 = 16,640 <= 20,480)
#define OFF_BIAS  (OFF_ABUF + SZ_ABUF)              // 219,136
#define OFF_SENSE (OFF_BIAS + NROWS * 4)            // 219,392
#define SMEM_BYTES (OFF_SENSE + 16)                 // 219,408

// Persistent state (device globals: allocation-free scratch)
__device__ float g_h0[BATCH * HID];
__device__ float g_h1[BATCH * HID];
__device__ float g_c [BATCH * HID];
__device__ volatile int g_sense;   // zero-init
__device__ int          g_count;   // zero-init

__global__ void init_state_kernel(const float* __restrict__ h0,
                                  const float* __restrict__ c0) {
    int i = blockIdx.x * blockDim.x + threadIdx.x;
    if (i < BATCH * HID) { g_h0[i] = h0[i]; g_c[i] = c0[i]; }
}

__device__ __forceinline__ uint32_t b2u(__nv_bfloat162 v) {
    return *reinterpret_cast<uint32_t*>(&v);
}

// split fp32 pair -> (hi bf16x2 word, lo bf16x2 word); low 16 bits = first (even-k) element
__device__ __forceinline__ void split2(float2 v, uint32_t& wh, uint32_t& wl) {
    __nv_bfloat162 hi2 = __floats2bfloat162_rn(v.x, v.y);
    float lx = v.x - __bfloat162float(__low2bfloat16(hi2));
    float ly = v.y - __bfloat162float(__high2bfloat16(hi2));
    __nv_bfloat162 lo2 = __floats2bfloat162_rn(lx, ly);
    wh = b2u(hi2); wl = b2u(lo2);
}

#define MMA_BF16(D, A, B0, B1)                                              \
    asm volatile("mma.sync.aligned.m16n8k16.row.col.f32.bf16.bf16.f32 "     \
                 "{%0,%1,%2,%3}, {%4,%5,%6,%7}, {%8,%9}, {%0,%1,%2,%3};"    \
                 : "+f"((D)[0]), "+f"((D)[1]), "+f"((D)[2]), "+f"((D)[3])   \
                 : "r"((A)[0]), "r"((A)[1]), "r"((A)[2]), "r"((A)[3]),      \
                   "r"(B0), "r"(B1));

// Persistent fused LSTM: tensor-core GEMM (bf16x3 ~ fp32), SMEM-resident weights,
// grid barrier between timesteps. Grid (32, 4) x 256 threads.
__global__ __launch_bounds__(256, 1)
void lstm_tc_kernel(const float* __restrict__ x_all,  // [T, BATCH, INP]
                    const float* __restrict__ W_ih,   // [4*HID, INP]
                    const float* __restrict__ W_hh,   // [4*HID, HID]
                    const float* __restrict__ b_ih,   // [4*HID]
                    const float* __restrict__ b_hh)   // [4*HID]
{
    extern __shared__ char sm[];
    uint32_t* Whi    = (uint32_t*)(sm + OFF_WHI);
    uint32_t* Wlo    = (uint32_t*)(sm + OFF_WLO);
    uint32_t* Ab     = (uint32_t*)(sm + OFF_ABUF);   // [(buf*2+hl)*BT + row]*A_STRIDE + col
    float*    gates  = (float*)   (sm + OFF_GATES);  // overlay on Ab
    float*    bias_s = (float*)   (sm + OFF_BIAS);
    int*      s_ls   = (int*)     (sm + OFF_SENSE);

    const int tid  = threadIdx.x;
    const int lane = tid & 31, warp = tid >> 5;
    const int wm = warp & 1;        // batch-half of the 64x64 tile
    const int wn = warp >> 1;       // 0..3: 16-gatecol slice
    const int lq  = lane >> 2;      // 0..7
    const int lr4 = lane & 3;       // 0..3
    const int jTile = blockIdx.x;   // 0..31
    const int bTile = blockIdx.y;   // 0..3

    // ---- one-time: load + split weights into SMEM (rows r = tt*16 + jj) ----
    {
        int r  = tid >> 2;                        // 0..63
        int grow = (r >> 4) * HID + jTile * JT + (r & 15);
        int kbase = (tid & 3) * 192;
        for (int i = 0; i < 96; ++i) {
            int k = kbase + 2 * i;
            float2 v = (k < INP)
                ? *(const float2*)(W_ih + (size_t)grow * INP + k)
                : *(const float2*)(W_hh + (size_t)grow * HID + (k - INP));
            uint32_t wh, wl; split2(v, wh, wl);
            Whi[r * W_STRIDE + k / 2] = wh;
            Wlo[r * W_STRIDE + k / 2] = wl;
        }
        if (tid < NROWS) {
            int gr = (tid >> 4) * HID + jTile * JT + (tid & 15);
            bias_s[tid] = b_ih[gr] + b_hh[gr];
        }
        if (tid == 0) *s_ls = g_sense;
    }
    __syncthreads();

    // staging assignment: 4 threads per batch row, 8 k-floats each
    const int srow  = tid >> 2;            // 0..63
    const int skoff = (tid & 3) * 8;       // k offset within chunk
    const int brow  = bTile * BT + srow;   // global batch row
    const int swc   = (tid & 3) * 4;       // word col base in A buf

    for (int t = 0; t < T_STEPS; ++t) {
        const float* __restrict__ x_t   = x_all + (size_t)t * BATCH * INP;
        const float* __restrict__ h_in  = (t & 1) ? g_h1 : g_h0;
        float*       __restrict__ h_out = (t & 1) ? g_h0 : g_h1;

        float d[2][2][4];
#pragma unroll
        for (int mf = 0; mf < 2; ++mf)
#pragma unroll
            for (int nf = 0; nf < 2; ++nf)
#pragma unroll
                for (int q = 0; q < 4; ++q) d[mf][nf][q] = 0.f;

        // ---- stage chunk 0 (pure x) into buffer 0 ----
        float2 pf[4];
        {
            const float* src = x_t + (size_t)brow * INP + skoff;
#pragma unroll
            for (int i = 0; i < 4; ++i) pf[i] = *(const float2*)(src + 2 * i);
#pragma unroll
            for (int i = 0; i < 4; ++i) {
                uint32_t wh, wl; split2(pf[i], wh, wl);
                Ab[(0) * BT * A_STRIDE + srow * A_STRIDE + swc + i] = wh;
                Ab[(1) * BT * A_STRIDE + srow * A_STRIDE + swc + i] = wl;
            }
        }
        __syncthreads();

        int buf = 0;
        for (int c = 0; c < NCH; ++c) {
            // prefetch next chunk into registers
            if (c < NCH - 1) {
                int kg = (c + 1) * KC + skoff;
                const float* src = (kg < INP)
                    ? (x_t  + (size_t)brow * INP + kg)
                    : (h_in + (size_t)brow * HID + (kg - INP));
#pragma unroll
                for (int i = 0; i < 4; ++i) pf[i] = *(const float2*)(src + 2 * i);
            }

            // MMA over the 2 k-steps (16 each) of this chunk
            const int base_h = (buf * 2 + 0) * BT * A_STRIDE;
            const int base_l = (buf * 2 + 1) * BT * A_STRIDE;
#pragma unroll
            for (int ks = 0; ks < 2; ++ks) {
                const int gw  = c * 16 + ks * 8 + lr4;   // weight word col
                uint32_t bh[2][2], bl[2][2];
#pragma unroll
                for (int nf = 0; nf < 2; ++nf) {
                    int r = wn * 16 + nf * 8 + lq;
                    bh[nf][0] = Whi[r * W_STRIDE + gw];
                    bh[nf][1] = Whi[r * W_STRIDE + gw + 4];
                    bl[nf][0] = Wlo[r * W_STRIDE + gw];
                    bl[nf][1] = Wlo[r * W_STRIDE + gw + 4];
                }
                const int wc0 = ks * 8 + lr4;
#pragma unroll
                for (int mf = 0; mf < 2; ++mf) {
                    int m0 = wm * 32 + mf * 16 + lq;
                    uint32_t ah[4], al[4];
                    ah[0] = Ab[base_h +  m0      * A_STRIDE + wc0];
                    ah[1] = Ab[base_h + (m0 + 8) * A_STRIDE + wc0];
                    ah[2] = Ab[base_h +  m0      * A_STRIDE + wc0 + 4];
                    ah[3] = Ab[base_h + (m0 + 8) * A_STRIDE + wc0 + 4];
                    al[0] = Ab[base_l +  m0      * A_STRIDE + wc0];
                    al[1] = Ab[base_l + (m0 + 8) * A_STRIDE + wc0];
                    al[2] = Ab[base_l +  m0      * A_STRIDE + wc0 + 4];
                    al[3] = Ab[base_l + (m0 + 8) * A_STRIDE + wc0 + 4];
#pragma unroll
                    for (int nf = 0; nf < 2; ++nf) {
                        MMA_BF16(d[mf][nf], ah, bh[nf][0], bh[nf][1]);  // hi*hi
                        MMA_BF16(d[mf][nf], ah, bl[nf][0], bl[nf][1]);  // hi*lo
                        MMA_BF16(d[mf][nf], al, bh[nf][0], bh[nf][1]);  // lo*hi
                    }
                }
            }

            // commit prefetched chunk into the other buffer
            if (c < NCH - 1) {
                int nbuf = buf ^ 1;
#pragma unroll
                for (int i = 0; i < 4; ++i) {
                    uint32_t wh, wl; split2(pf[i], wh, wl);
                    Ab[(nbuf * 2 + 0) * BT * A_STRIDE + srow * A_STRIDE + swc + i] = wh;
                    Ab[(nbuf * 2 + 1) * BT * A_STRIDE + srow * A_STRIDE + swc + i] = wl;
                }
            }
            __syncthreads();
            buf ^= 1;
        }

        // ---- spill accumulators to SMEM gates buffer (overlays A bufs) ----
#pragma unroll
        for (int mf = 0; mf < 2; ++mf)
#pragma unroll
            for (int nf = 0; nf < 2; ++nf) {
                int m = wm * 32 + mf * 16 + lq;
                int n = wn * 16 + nf * 8 + lr4 * 2;
                gates[ m      * G_STRIDE + n    ] = d[mf][nf][0];
                gates[ m      * G_STRIDE + n + 1] = d[mf][nf][1];
                gates[(m + 8) * G_STRIDE + n    ] = d[mf][nf][2];
                gates[(m + 8) * G_STRIDE + n + 1] = d[mf][nf][3];
            }
        __syncthreads();

        // ---- fused LSTM epilogue: thread owns 4 (b, j) cells ----
        {
            int b  = tid >> 2;
            int bg = bTile * BT + b;
#pragma unroll
            for (int i = 0; i < 4; ++i) {
                int j  = (tid & 3) * 4 + i;
                float gi = gates[b * G_STRIDE + j]      + bias_s[j];
                float gf = gates[b * G_STRIDE + 16 + j] + bias_s[16 + j];
                float gg = gates[b * G_STRIDE + 32 + j] + bias_s[32 + j];
                float go = gates[b * G_STRIDE + 48 + j] + bias_s[48 + j];
                float iv = 1.f / (1.f + expf(-gi));
                float fv = 1.f / (1.f + expf(-gf));
                float gv = tanhf(gg);
                float ov = 1.f / (1.f + expf(-go));
                int   jg = jTile * JT + j;
                size_t idx = (size_t)bg * HID + jg;
                float cn = fv * g_c[idx] + iv * gv;
                g_c[idx]   = cn;
                h_out[idx] = ov * tanhf(cn);
            }
        }

        // ---- grid barrier (sense-reversing): publish h_out to all blocks ----
        __syncthreads();
        if (tid == 0) {
            int ls = *s_ls ^ 1;
            *s_ls = ls;
            __threadfence();
            if (atomicAdd(&g_count, 1) == NBLK - 1) {
                g_count = 0;
                __threadfence();
                g_sense = ls;
            } else {
                while (g_sense != ls) { }
                __threadfence();
            }
        }
        __syncthreads();
    }
}

// out[b] = h_last[b] . W_dec + b_dec   (h_last lives in g_h0 after 2048 steps)
__global__ void decode_kernel(const float* __restrict__ W_dec,
                              const float* __restrict__ b_dec,
                              float* __restrict__ out)
{
    int b = blockIdx.x;
    float s = 0.f;
    for (int k = threadIdx.x; k < HID; k += 128)
        s += g_h0[(size_t)b * HID + k] * W_dec[k];
    __shared__ float red[128];
    red[threadIdx.x] = s;
    __syncthreads();
#pragma unroll
    for (int off = 64; off > 0; off >>= 1) {
        if (threadIdx.x < off) red[threadIdx.x] += red[threadIdx.x + off];
        __syncthreads();
    }
    if (threadIdx.x == 0) out[b] = red[0] + b_dec[0];
}

extern "C" void kernel_launch(void* const* d_in, const int* in_sizes, int n_in,
                              void* d_out, int out_size)
{
    (void)in_sizes; (void)n_in; (void)out_size;
    const float* x     = (const float*)d_in[0];  // [T, B, I]
    const float* h0    = (const float*)d_in[1];  // [B, H]
    const float* c0    = (const float*)d_in[2];  // [B, H]
    const float* W_ih  = (const float*)d_in[3];  // [4H, I]
    const float* W_hh  = (const float*)d_in[4];  // [4H, H]
    const float* b_ih  = (const float*)d_in[5];  // [4H]
    const float* b_hh  = (const float*)d_in[6];  // [4H]
    const float* W_dec = (const float*)d_in[7];  // [1, H]
    const float* b_dec = (const float*)d_in[8];  // [1]
    float* out = (float*)d_out;                  // [B, 1]

    static bool attr_set = false;
    if (!attr_set) {
        cudaFuncSetAttribute(lstm_tc_kernel,
                             cudaFuncAttributeMaxDynamicSharedMemorySize, SMEM_BYTES);
        attr_set = true;
    }

    init_state_kernel<<<(BATCH * HID + 255) / 256, 256>>>(h0, c0);

    dim3 grid(HID / JT, BATCH / BT);   // (32, 4) = 128 blocks, all co-resident
    lstm_tc_kernel<<<grid, 256, SMEM_BYTES>>>(x, W_ih, W_hh, b_ih, b_hh);

    decode_kernel<<<BATCH, 128>>>(W_dec, b_dec, out);
}

// round 9
// speedup vs baseline: 1.0201x; 1.0050x over previous
#include <cuda_runtime.h>
#include <cuda_bf16.h>
#include <math.h>
#include <stdint.h>

// Problem dims (fixed by dataset)
#define T_STEPS 2048
#define BATCH   256
#define INP     256
#define HID     512
#define KTOT    768            // concat K: [x_t | h]

// Partition: block = (jTile, bTile): 16 hidden cols x 64 batch rows
#define JT 16                  // hidden columns per block
#define BT 64                  // batch rows per block
#define NROWS 64               // gate rows per block = 4 gates * JT
#define KC 32                  // K chunk staged per iteration
#define NCH (KTOT / KC)        // 24 chunks
#define NBLK 128               // 32 x 4 grid, all co-resident (<=148 SMs)

// SMEM strides (in 32-bit words), padded for conflict-free fragment loads
#define W_STRIDE 388           // 384 words (768 bf16) + 4 pad  -> stride%32==4
#define A_STRIDE 20            // 16 words (32 bf16)  + 4 pad  -> stride%32==20
#define G_STRIDE 65            // gates buffer row stride (floats)

// SMEM layout (bytes)
#define SZ_W      (NROWS * W_STRIDE * 4)            // 99,328
#define OFF_WHI   0
#define OFF_WLO   (OFF_WHI + SZ_W)                  // 99,328
#define OFF_ABUF  (OFF_WLO + SZ_W)                  // 198,656
#define SZ_ABUF   (2 * 2 * BT * A_STRIDE * 4)       // 20,480 (dbuf x hi/lo x 64 x 20)
#define OFF_GATES OFF_ABUF                          // overlay (64*65*4 = 16,640 <= 20,480)
#define OFF_BIAS  (OFF_ABUF + SZ_ABUF)              // 219,136
#define OFF_SENSE (OFF_BIAS + NROWS * 4)            // 219,392
#define SMEM_BYTES (OFF_SENSE + 16)                 // 219,408

// Persistent state (device globals: allocation-free scratch)
__device__ float g_h0[BATCH * HID];
__device__ float g_h1[BATCH * HID];
__device__ float g_c [BATCH * HID];
__device__ volatile int g_sense;   // zero-init
__device__ int          g_count;   // zero-init

__global__ void init_state_kernel(const float* __restrict__ h0,
                                  const float* __restrict__ c0) {
    int i = blockIdx.x * blockDim.x + threadIdx.x;
    if (i < BATCH * HID) { g_h0[i] = h0[i]; g_c[i] = c0[i]; }
}

__device__ __forceinline__ uint32_t b2u(__nv_bfloat162 v) {
    return *reinterpret_cast<uint32_t*>(&v);
}

// split fp32 pair -> (hi bf16x2 word, lo bf16x2 word); low 16 bits = first (even-k) element
__device__ __forceinline__ void split2(float2 v, uint32_t& wh, uint32_t& wl) {
    __nv_bfloat162 hi2 = __floats2bfloat162_rn(v.x, v.y);
    float lx = v.x - __bfloat162float(__low2bfloat16(hi2));
    float ly = v.y - __bfloat162float(__high2bfloat16(hi2));
    __nv_bfloat162 lo2 = __floats2bfloat162_rn(lx, ly);
    wh = b2u(hi2); wl = b2u(lo2);
}

#define MMA_BF16(D, A, B0, B1)                                              \
    asm volatile("mma.sync.aligned.m16n8k16.row.col.f32.bf16.bf16.f32 "     \
                 "{%0,%1,%2,%3}, {%4,%5,%6,%7}, {%8,%9}, {%0,%1,%2,%3};"    \
                 : "+f"((D)[0]), "+f"((D)[1]), "+f"((D)[2]), "+f"((D)[3])   \
                 : "r"((A)[0]), "r"((A)[1]), "r"((A)[2]), "r"((A)[3]),      \
                   "r"(B0), "r"(B1));

// Persistent fused LSTM: tensor-core GEMM (bf16x3 ~ fp32), SMEM-resident weights,
// grid barrier between timesteps. Grid (32, 4) x 256 threads.
__global__ __launch_bounds__(256, 1)
void lstm_tc_kernel(const float* __restrict__ x_all,  // [T, BATCH, INP]
                    const float* __restrict__ W_ih,   // [4*HID, INP]
                    const float* __restrict__ W_hh,   // [4*HID, HID]
                    const float* __restrict__ b_ih,   // [4*HID]
                    const float* __restrict__ b_hh)   // [4*HID]
{
    extern __shared__ char sm[];
    uint32_t* Whi    = (uint32_t*)(sm + OFF_WHI);
    uint32_t* Wlo    = (uint32_t*)(sm + OFF_WLO);
    uint32_t* Ab     = (uint32_t*)(sm + OFF_ABUF);   // [(buf*2+hl)*BT + row]*A_STRIDE + col
    float*    gates  = (float*)   (sm + OFF_GATES);  // overlay on Ab
    float*    bias_s = (float*)   (sm + OFF_BIAS);
    int*      s_ls   = (int*)     (sm + OFF_SENSE);

    const int tid  = threadIdx.x;
    const int lane = tid & 31, warp = tid >> 5;
    const int wm = warp & 1;        // batch-half of the 64x64 tile
    const int wn = warp >> 1;       // 0..3: 16-gatecol slice
    const int lq  = lane >> 2;      // 0..7
    const int lr4 = lane & 3;       // 0..3
    const int jTile = blockIdx.x;   // 0..31
    const int bTile = blockIdx.y;   // 0..3

    // ---- one-time: load + split weights into SMEM (rows r = tt*16 + jj) ----
    {
        int r  = tid >> 2;                        // 0..63
        int grow = (r >> 4) * HID + jTile * JT + (r & 15);
        int kbase = (tid & 3) * 192;
        for (int i = 0; i < 96; ++i) {
            int k = kbase + 2 * i;
            float2 v = (k < INP)
                ? *(const float2*)(W_ih + (size_t)grow * INP + k)
                : *(const float2*)(W_hh + (size_t)grow * HID + (k - INP));
            uint32_t wh, wl; split2(v, wh, wl);
            Whi[r * W_STRIDE + k / 2] = wh;
            Wlo[r * W_STRIDE + k / 2] = wl;
        }
        if (tid < NROWS) {
            int gr = (tid >> 4) * HID + jTile * JT + (tid & 15);
            bias_s[tid] = b_ih[gr] + b_hh[gr];
        }
        if (tid == 0) *s_ls = g_sense;
    }
    __syncthreads();

    // staging assignment: 4 threads per batch row, 8 k-floats each
    const int srow  = tid >> 2;            // 0..63
    const int skoff = (tid & 3) * 8;       // k offset within chunk
    const int brow  = bTile * BT + srow;   // global batch row
    const int swc   = (tid & 3) * 4;       // word col base in A buf

    for (int t = 0; t < T_STEPS; ++t) {
        const float* __restrict__ x_t   = x_all + (size_t)t * BATCH * INP;
        const float* __restrict__ h_in  = (t & 1) ? g_h1 : g_h0;
        float*       __restrict__ h_out = (t & 1) ? g_h0 : g_h1;

        float d[2][2][4];
#pragma unroll
        for (int mf = 0; mf < 2; ++mf)
#pragma unroll
            for (int nf = 0; nf < 2; ++nf)
#pragma unroll
                for (int q = 0; q < 4; ++q) d[mf][nf][q] = 0.f;

        // ---- stage chunk 0 (pure x) into buffer 0 ----
        float2 pf[4];
        {
            const float* src = x_t + (size_t)brow * INP + skoff;
#pragma unroll
            for (int i = 0; i < 4; ++i) pf[i] = *(const float2*)(src + 2 * i);
#pragma unroll
            for (int i = 0; i < 4; ++i) {
                uint32_t wh, wl; split2(pf[i], wh, wl);
                Ab[(0) * BT * A_STRIDE + srow * A_STRIDE + swc + i] = wh;
                Ab[(1) * BT * A_STRIDE + srow * A_STRIDE + swc + i] = wl;
            }
        }
        __syncthreads();

        int buf = 0;
        for (int c = 0; c < NCH; ++c) {
            // prefetch next chunk into registers
            if (c < NCH - 1) {
                int kg = (c + 1) * KC + skoff;
                const float* src = (kg < INP)
                    ? (x_t  + (size_t)brow * INP + kg)
                    : (h_in + (size_t)brow * HID + (kg - INP));
#pragma unroll
                for (int i = 0; i < 4; ++i) pf[i] = *(const float2*)(src + 2 * i);
            }

            // MMA over the 2 k-steps (16 each) of this chunk
            const int base_h = (buf * 2 + 0) * BT * A_STRIDE;
            const int base_l = (buf * 2 + 1) * BT * A_STRIDE;
#pragma unroll
            for (int ks = 0; ks < 2; ++ks) {
                const int gw  = c * 16 + ks * 8 + lr4;   // weight word col
                uint32_t bh[2][2], bl[2][2];
#pragma unroll
                for (int nf = 0; nf < 2; ++nf) {
                    int r = wn * 16 + nf * 8 + lq;
                    bh[nf][0] = Whi[r * W_STRIDE + gw];
                    bh[nf][1] = Whi[r * W_STRIDE + gw + 4];
                    bl[nf][0] = Wlo[r * W_STRIDE + gw];
                    bl[nf][1] = Wlo[r * W_STRIDE + gw + 4];
                }
                const int wc0 = ks * 8 + lr4;
#pragma unroll
                for (int mf = 0; mf < 2; ++mf) {
                    int m0 = wm * 32 + mf * 16 + lq;
                    uint32_t ah[4], al[4];
                    ah[0] = Ab[base_h +  m0      * A_STRIDE + wc0];
                    ah[1] = Ab[base_h + (m0 + 8) * A_STRIDE + wc0];
                    ah[2] = Ab[base_h +  m0      * A_STRIDE + wc0 + 4];
                    ah[3] = Ab[base_h + (m0 + 8) * A_STRIDE + wc0 + 4];
                    al[0] = Ab[base_l +  m0      * A_STRIDE + wc0];
                    al[1] = Ab[base_l + (m0 + 8) * A_STRIDE + wc0];
                    al[2] = Ab[base_l +  m0      * A_STRIDE + wc0 + 4];
                    al[3] = Ab[base_l + (m0 + 8) * A_STRIDE + wc0 + 4];
#pragma unroll
                    for (int nf = 0; nf < 2; ++nf) {
                        MMA_BF16(d[mf][nf], ah, bh[nf][0], bh[nf][1]);  // hi*hi
                        MMA_BF16(d[mf][nf], ah, bl[nf][0], bl[nf][1]);  // hi*lo
                        MMA_BF16(d[mf][nf], al, bh[nf][0], bh[nf][1]);  // lo*hi
                    }
                }
            }

            // commit prefetched chunk into the other buffer
            if (c < NCH - 1) {
                int nbuf = buf ^ 1;
#pragma unroll
                for (int i = 0; i < 4; ++i) {
                    uint32_t wh, wl; split2(pf[i], wh, wl);
                    Ab[(nbuf * 2 + 0) * BT * A_STRIDE + srow * A_STRIDE + swc + i] = wh;
                    Ab[(nbuf * 2 + 1) * BT * A_STRIDE + srow * A_STRIDE + swc + i] = wl;
                }
            }
            __syncthreads();
            buf ^= 1;
        }

        // ---- spill accumulators to SMEM gates buffer (overlays A bufs) ----
#pragma unroll
        for (int mf = 0; mf < 2; ++mf)
#pragma unroll
            for (int nf = 0; nf < 2; ++nf) {
                int m = wm * 32 + mf * 16 + lq;
                int n = wn * 16 + nf * 8 + lr4 * 2;
                gates[ m      * G_STRIDE + n    ] = d[mf][nf][0];
                gates[ m      * G_STRIDE + n + 1] = d[mf][nf][1];
                gates[(m + 8) * G_STRIDE + n    ] = d[mf][nf][2];
                gates[(m + 8) * G_STRIDE + n + 1] = d[mf][nf][3];
            }
        __syncthreads();

        // ---- fused LSTM epilogue: thread owns 4 (b, j) cells ----
        {
            int b  = tid >> 2;
            int bg = bTile * BT + b;
#pragma unroll
            for (int i = 0; i < 4; ++i) {
                int j  = (tid & 3) * 4 + i;
                float gi = gates[b * G_STRIDE + j]      + bias_s[j];
                float gf = gates[b * G_STRIDE + 16 + j] + bias_s[16 + j];
                float gg = gates[b * G_STRIDE + 32 + j] + bias_s[32 + j];
                float go = gates[b * G_STRIDE + 48 + j] + bias_s[48 + j];
                float iv = 1.f / (1.f + expf(-gi));
                float fv = 1.f / (1.f + expf(-gf));
                float gv = tanhf(gg);
                float ov = 1.f / (1.f + expf(-go));
                int   jg = jTile * JT + j;
                size_t idx = (size_t)bg * HID + jg;
                float cn = fv * g_c[idx] + iv * gv;
                g_c[idx]   = cn;
                h_out[idx] = ov * tanhf(cn);
            }
        }

        // ---- grid barrier (sense-reversing): publish h_out to all blocks ----
        __syncthreads();
        if (tid == 0) {
            int ls = *s_ls ^ 1;
            *s_ls = ls;
            __threadfence();
            if (atomicAdd(&g_count, 1) == NBLK - 1) {
                g_count = 0;
                __threadfence();
                g_sense = ls;
            } else {
                while (g_sense != ls) { }
                __threadfence();
            }
        }
        __syncthreads();
    }
}

// out[b] = h_last[b] . W_dec + b_dec   (h_last lives in g_h0 after 2048 steps)
__global__ void decode_kernel(const float* __restrict__ W_dec,
                              const float* __restrict__ b_dec,
                              float* __restrict__ out)
{
    int b = blockIdx.x;
    float s = 0.f;
    for (int k = threadIdx.x; k < HID; k += 128)
        s += g_h0[(size_t)b * HID + k] * W_dec[k];
    __shared__ float red[128];
    red[threadIdx.x] = s;
    __syncthreads();
#pragma unroll
    for (int off = 64; off > 0; off >>= 1) {
        if (threadIdx.x < off) red[threadIdx.x] += red[threadIdx.x + off];
        __syncthreads();
    }
    if (threadIdx.x == 0) out[b] = red[0] + b_dec[0];
}

extern "C" void kernel_launch(void* const* d_in, const int* in_sizes, int n_in,
                              void* d_out, int out_size)
{
    (void)in_sizes; (void)n_in; (void)out_size;
    const float* x     = (const float*)d_in[0];  // [T, B, I]
    const float* h0    = (const float*)d_in[1];  // [B, H]
    const float* c0    = (const float*)d_in[2];  // [B, H]
    const float* W_ih  = (const float*)d_in[3];  // [4H, I]
    const float* W_hh  = (const float*)d_in[4];  // [4H, H]
    const float* b_ih  = (const float*)d_in[5];  // [4H]
    const float* b_hh  = (const float*)d_in[6];  // [4H]
    const float* W_dec = (const float*)d_in[7];  // [1, H]
    const float* b_dec = (const float*)d_in[8];  // [1]
    float* out = (float*)d_out;                  // [B, 1]

    static bool attr_set = false;
    if (!attr_set) {
        cudaFuncSetAttribute(lstm_tc_kernel,
                             cudaFuncAttributeMaxDynamicSharedMemorySize, SMEM_BYTES);
        attr_set = true;
    }

    init_state_kernel<<<(BATCH * HID + 255) / 256, 256>>>(h0, c0);

    dim3 grid(HID / JT, BATCH / BT);   // (32, 4) = 128 blocks, all co-resident
    lstm_tc_kernel<<<grid, 256, SMEM_BYTES>>>(x, W_ih, W_hh, b_ih, b_hh);

    decode_kernel<<<BATCH, 128>>>(W_dec, b_dec, out);
}

// round 10
// speedup vs baseline: 1.4512x; 1.4226x over previous
#include <cuda_runtime.h>
#include <cuda_bf16.h>
#include <math.h>
#include <stdint.h>

// Problem dims (fixed by dataset)
#define T_STEPS 2048
#define BATCH   256
#define INP     256
#define HID     512
#define KTOT    768            // concat K: [x_t | h]

// Partition: block = (jTile, bTile): 16 hidden cols x 64 batch rows
#define JT 16
#define BT 64
#define NROWS 64               // 4 gates * JT weight rows per block
#define KC 32                  // K chunk per stage
#define NCH (KTOT / KC)        // 24 chunks (0-7 = x, 8-23 = h)
#define NBG 32                 // blocks per barrier group (all jTiles of one bTile)

// SMEM strides (32-bit words); stride % 32 == 4 or 20 -> conflict-free ldmatrix rows
#define W_STRIDE 388
#define A_STRIDE 20
#define G_STRIDE 65
#define ABUF_PLANE (BT * A_STRIDE)        // 1280 words per (buf,hl) plane

#define SZ_W      (NROWS * W_STRIDE * 4)  // 99,328 B
#define OFF_WHI   0
#define OFF_WLO   (OFF_WHI + SZ_W)
#define OFF_ABUF  (OFF_WLO + SZ_W)        // 198,656
#define SZ_ABUF   (2 * 2 * ABUF_PLANE * 4)// 20,480 B
#define OFF_GATES OFF_ABUF                // overlay (64*65*4 = 16,640 <= 20,480)
#define OFF_BIAS  (OFF_ABUF + SZ_ABUF)    // 219,136
#define SMEM_BYTES (OFF_BIAS + NROWS * 4 + 16)

// Persistent state: h double-buffered, PRE-SPLIT into bf16 hi/lo packed words
__device__ uint32_t g_hhi[2][BATCH * HID / 2];
__device__ uint32_t g_hlo[2][BATCH * HID / 2];
// Per-group sense barriers (zero-init)
__device__ volatile int g_sense4[4];
__device__ int          g_count4[4];

__device__ __forceinline__ uint32_t b2u(__nv_bfloat162 v) {
    return *reinterpret_cast<uint32_t*>(&v);
}
__device__ __forceinline__ void split2(float2 v, uint32_t& wh, uint32_t& wl) {
    __nv_bfloat162 hi2 = __floats2bfloat162_rn(v.x, v.y);
    float lx = v.x - __bfloat162float(__low2bfloat16(hi2));
    float ly = v.y - __bfloat162float(__high2bfloat16(hi2));
    wh = b2u(hi2); wl = b2u(__floats2bfloat162_rn(lx, ly));
}
__device__ __forceinline__ float fast_sigmoid(float x) {
    x = fminf(fmaxf(x, -30.f), 30.f);
    return __fdividef(1.f, 1.f + __expf(-x));
}
__device__ __forceinline__ float fast_tanh(float x) {
    x = fminf(fmaxf(x, -15.f), 15.f);
    float e = __expf(2.f * x);
    return __fdividef(e - 1.f, e + 1.f);
}

__device__ __forceinline__ void ldsm4(uint32_t* r, uint32_t saddr) {
    asm volatile("ldmatrix.sync.aligned.m8n8.x4.shared.b16 {%0,%1,%2,%3}, [%4];"
                 : "=r"(r[0]), "=r"(r[1]), "=r"(r[2]), "=r"(r[3]) : "r"(saddr));
}
#define MMA_BF16(D, A, B0, B1)                                              \
    asm volatile("mma.sync.aligned.m16n8k16.row.col.f32.bf16.bf16.f32 "     \
                 "{%0,%1,%2,%3}, {%4,%5,%6,%7}, {%8,%9}, {%0,%1,%2,%3};"    \
                 : "+f"((D)[0]), "+f"((D)[1]), "+f"((D)[2]), "+f"((D)[3])   \
                 : "r"((A)[0]), "r"((A)[1]), "r"((A)[2]), "r"((A)[3]),      \
                   "r"(B0), "r"(B1));

// ONE kernel: init + 2048 fused LSTM steps + decode. Grid (32,4) x 256 threads.
__global__ __launch_bounds__(256, 1)
void lstm_all_kernel(const float* __restrict__ x_all,  // [T, BATCH, INP]
                     const float* __restrict__ h0,
                     const float* __restrict__ c0,
                     const float* __restrict__ W_ih,   // [4H, INP]
                     const float* __restrict__ W_hh,   // [4H, HID]
                     const float* __restrict__ b_ih,
                     const float* __restrict__ b_hh,
                     const float* __restrict__ W_dec,  // [1, HID]
                     const float* __restrict__ b_dec,
                     float* __restrict__ out)          // [BATCH, 1]
{
    extern __shared__ char sm[];
    uint32_t* Whi    = (uint32_t*)(sm + OFF_WHI);
    uint32_t* Wlo    = (uint32_t*)(sm + OFF_WLO);
    uint32_t* Ab     = (uint32_t*)(sm + OFF_ABUF);
    float*    gates  = (float*)   (sm + OFF_GATES);
    float*    bias_s = (float*)   (sm + OFF_BIAS);

    const int tid  = threadIdx.x;
    const int lane = tid & 31, warp = tid >> 5;
    const int wm = warp & 1;         // batch half of 64x64 tile
    const int wn = warp >> 1;        // 16-col slice
    const int jTile = blockIdx.x;    // 0..31
    const int bTile = blockIdx.y;    // 0..3 (= barrier group)

    // ---- one-time: load + split weights; biases ----
    {
        int r = tid >> 2;
        int grow = (r >> 4) * HID + jTile * JT + (r & 15);
        int kbase = (tid & 3) * 192;
        for (int i = 0; i < 96; ++i) {
            int k = kbase + 2 * i;
            float2 v = (k < INP)
                ? *(const float2*)(W_ih + (size_t)grow * INP + k)
                : *(const float2*)(W_hh + (size_t)grow * HID + (k - INP));
            uint32_t wh, wl; split2(v, wh, wl);
            Whi[r * W_STRIDE + k / 2] = wh;
            Wlo[r * W_STRIDE + k / 2] = wl;
        }
        if (tid < NROWS) {
            int gr = (tid >> 4) * HID + jTile * JT + (tid & 15);
            bias_s[tid] = b_ih[gr] + b_hh[gr];
        }
    }

    // ---- epilogue/ownership mapping (step-invariant): 4 cells per thread ----
    const int eb  = tid >> 2;                 // local batch row 0..63
    const int ebg = bTile * BT + eb;          // global batch row
    const int ej0 = (tid & 3) * 4;            // local j base (0..12)
    const int jg0 = jTile * JT + ej0;         // global hidden col base
    const int hw0 = ebg * (HID / 2) + jg0 / 2;// word index of (ebg, jg0)

    // init h (split to hi/lo set 0) + c in registers
    float creg[4];
    {
        float4 hv = *(const float4*)(h0 + (size_t)ebg * HID + jg0);
        float4 cv = *(const float4*)(c0 + (size_t)ebg * HID + jg0);
        creg[0] = cv.x; creg[1] = cv.y; creg[2] = cv.z; creg[3] = cv.w;
        uint32_t h0h, h0l, h1h, h1l;
        split2(make_float2(hv.x, hv.y), h0h, h0l);
        split2(make_float2(hv.z, hv.w), h1h, h1l);
        g_hhi[0][hw0] = h0h; g_hhi[0][hw0 + 1] = h1h;
        g_hlo[0][hw0] = h0l; g_hlo[0][hw0 + 1] = h1l;
    }

    int my_sense = g_sense4[bTile];   // stable: only this kernel's barriers flip it
    __syncthreads();

    // group barrier helper (inlined twice below)
#define GROUP_BARRIER()                                                     \
    do {                                                                    \
        __syncthreads();                                                    \
        if (tid == 0) {                                                     \
            my_sense ^= 1;                                                  \
            __threadfence();                                                \
            if (atomicAdd(&g_count4[bTile], 1) == NBG - 1) {                \
                g_count4[bTile] = 0;                                        \
                __threadfence();                                            \
                g_sense4[bTile] = my_sense;                                 \
            } else {                                                        \
                while (g_sense4[bTile] != my_sense) { }                     \
                __threadfence();                                            \
            }                                                               \
        }                                                                   \
        __syncthreads();                                                    \
    } while (0)

    GROUP_BARRIER();   // publish h init

    // ---- ldmatrix lane addressing (bytes, shared space) ----
    const uint32_t ab_sh  = (uint32_t)__cvta_generic_to_shared(Ab);
    const uint32_t whi_sh = (uint32_t)__cvta_generic_to_shared(Whi);
    const uint32_t wlo_sh = (uint32_t)__cvta_generic_to_shared(Wlo);
    const int rowoff = (lane & 7) + ((lane >> 3) & 1) * 8;
    const int khalf4 = (lane >> 4) * 4;    // word offset for k-half
    const uint32_t wlane_hi = whi_sh + ((wn * 16 + rowoff) * W_STRIDE + khalf4) * 4;
    const uint32_t wlane_lo = wlo_sh + ((wn * 16 + rowoff) * W_STRIDE + khalf4) * 4;
    uint32_t alane[2];   // per mf
#pragma unroll
    for (int mf = 0; mf < 2; ++mf)
        alane[mf] = ab_sh + ((wm * 32 + mf * 16 + rowoff) * A_STRIDE + khalf4) * 4;

    // staging: 4 threads per row, 8 k-floats (= 4 words) each
    const int srow = tid >> 2;
    const int skw  = (tid & 3) * 4;            // word col in A plane
    const int brow = bTile * BT + srow;
    const int sdst = srow * A_STRIDE + skw;    // word offset within plane

    for (int t = 0; t < T_STEPS; ++t) {
        const float* __restrict__ x_t = x_all + (size_t)t * BATCH * INP;
        const uint32_t* __restrict__ hhi_in = g_hhi[t & 1];
        const uint32_t* __restrict__ hlo_in = g_hlo[t & 1];
        uint32_t* __restrict__ hhi_out = g_hhi[(t & 1) ^ 1];
        uint32_t* __restrict__ hlo_out = g_hlo[(t & 1) ^ 1];

        float d[2][2][4];
#pragma unroll
        for (int mf = 0; mf < 2; ++mf)
#pragma unroll
            for (int nf = 0; nf < 2; ++nf)
#pragma unroll
                for (int q = 0; q < 4; ++q) d[mf][nf][q] = 0.f;

        // stage chunk 0 (pure x) into buf 0
        {
            const float* src = x_t + (size_t)brow * INP + skw * 2;
            float4 v0 = *(const float4*)(src);
            float4 v1 = *(const float4*)(src + 4);
            uint4 h4, l4;
            split2(make_float2(v0.x, v0.y), h4.x, l4.x);
            split2(make_float2(v0.z, v0.w), h4.y, l4.y);
            split2(make_float2(v1.x, v1.y), h4.z, l4.z);
            split2(make_float2(v1.z, v1.w), h4.w, l4.w);
            *(uint4*)&Ab[0 * ABUF_PLANE + sdst] = h4;
            *(uint4*)&Ab[1 * ABUF_PLANE + sdst] = l4;
        }
        __syncthreads();

        int buf = 0;
        for (int c = 0; c < NCH; ++c) {
            // ---- prefetch chunk c+1 ----
            uint4 pre_h, pre_l;   // committed words (hi, lo)
            float4 pv0, pv1;
            bool next_is_x = (c + 1 < 8);
            if (c < NCH - 1) {
                if (next_is_x) {
                    const float* src = x_t + (size_t)brow * INP + (c + 1) * KC + skw * 2;
                    pv0 = *(const float4*)(src);
                    pv1 = *(const float4*)(src + 4);
                } else {
                    int off = brow * (HID / 2) + (c + 1 - 8) * 16 + skw;
                    pre_h = *(const uint4*)&hhi_in[off];
                    pre_l = *(const uint4*)&hlo_in[off];
                }
            }

            // ---- MMA on chunk c (ldmatrix fragments) ----
            const uint32_t abase_h = (uint32_t)((buf * 2 + 0) * ABUF_PLANE * 4);
            const uint32_t abase_l = (uint32_t)((buf * 2 + 1) * ABUF_PLANE * 4);
#pragma unroll
            for (int ks = 0; ks < 2; ++ks) {
                const uint32_t wkoff = (uint32_t)((c * 16 + ks * 8) * 4);
                uint32_t bh[4], bl[4];
                ldsm4(bh, wlane_hi + wkoff);   // [nf0.k0-7, nf1.k0-7, nf0.k8-15, nf1.k8-15]
                ldsm4(bl, wlane_lo + wkoff);
#pragma unroll
                for (int mf = 0; mf < 2; ++mf) {
                    uint32_t ah[4], al[4];
                    ldsm4(ah, alane[mf] + abase_h + (uint32_t)(ks * 32));
                    ldsm4(al, alane[mf] + abase_l + (uint32_t)(ks * 32));
                    MMA_BF16(d[mf][0], ah, bh[0], bh[2]);   // hi*hi
                    MMA_BF16(d[mf][1], ah, bh[1], bh[3]);
                    MMA_BF16(d[mf][0], ah, bl[0], bl[2]);   // hi*lo
                    MMA_BF16(d[mf][1], ah, bl[1], bl[3]);
                    MMA_BF16(d[mf][0], al, bh[0], bh[2]);   // lo*hi
                    MMA_BF16(d[mf][1], al, bh[1], bh[3]);
                }
            }

            // ---- commit prefetched chunk ----
            if (c < NCH - 1) {
                int nb = buf ^ 1;
                if (next_is_x) {
                    uint4 h4, l4;
                    split2(make_float2(pv0.x, pv0.y), h4.x, l4.x);
                    split2(make_float2(pv0.z, pv0.w), h4.y, l4.y);
                    split2(make_float2(pv1.x, pv1.y), h4.z, l4.z);
                    split2(make_float2(pv1.z, pv1.w), h4.w, l4.w);
                    *(uint4*)&Ab[(nb * 2 + 0) * ABUF_PLANE + sdst] = h4;
                    *(uint4*)&Ab[(nb * 2 + 1) * ABUF_PLANE + sdst] = l4;
                } else {
                    *(uint4*)&Ab[(nb * 2 + 0) * ABUF_PLANE + sdst] = pre_h;
                    *(uint4*)&Ab[(nb * 2 + 1) * ABUF_PLANE + sdst] = pre_l;
                }
            }
            __syncthreads();
            buf ^= 1;
        }

        // ---- spill accumulators to gates buffer (overlays A bufs) ----
        {
            const int lq = lane >> 2, lr4 = lane & 3;
#pragma unroll
            for (int mf = 0; mf < 2; ++mf)
#pragma unroll
                for (int nf = 0; nf < 2; ++nf) {
                    int m = wm * 32 + mf * 16 + lq;
                    int n = wn * 16 + nf * 8 + lr4 * 2;
                    gates[ m      * G_STRIDE + n    ] = d[mf][nf][0];
                    gates[ m      * G_STRIDE + n + 1] = d[mf][nf][1];
                    gates[(m + 8) * G_STRIDE + n    ] = d[mf][nf][2];
                    gates[(m + 8) * G_STRIDE + n + 1] = d[mf][nf][3];
                }
        }
        __syncthreads();

        // ---- LSTM epilogue: c in regs, h split+stored as bf16 hi/lo ----
        {
            float hnew[4];
#pragma unroll
            for (int i = 0; i < 4; ++i) {
                int j = ej0 + i;
                float gi = gates[eb * G_STRIDE + j]      + bias_s[j];
                float gf = gates[eb * G_STRIDE + 16 + j] + bias_s[16 + j];
                float gg = gates[eb * G_STRIDE + 32 + j] + bias_s[32 + j];
                float go = gates[eb * G_STRIDE + 48 + j] + bias_s[48 + j];
                float iv = fast_sigmoid(gi);
                float fv = fast_sigmoid(gf);
                float gv = fast_tanh(gg);
                float ov = fast_sigmoid(go);
                float cn = fv * creg[i] + iv * gv;
                creg[i] = cn;
                hnew[i] = ov * fast_tanh(cn);
            }
            uint32_t h0h, h0l, h1h, h1l;
            split2(make_float2(hnew[0], hnew[1]), h0h, h0l);
            split2(make_float2(hnew[2], hnew[3]), h1h, h1l);
            *(uint2*)&hhi_out[hw0] = make_uint2(h0h, h1h);
            *(uint2*)&hlo_out[hw0] = make_uint2(h0l, h1l);
        }

        GROUP_BARRIER();   // publish h to the bTile group
    }

    // ---- decode by jTile==0 blocks: out[b] = h_last . W_dec + b_dec ----
    if (jTile == 0) {
        // h_last in set 0 (after t=2047, write set = 0)
        const uint32_t* __restrict__ hh = g_hhi[0];
        const uint32_t* __restrict__ hl = g_hlo[0];
        int b = bTile * BT + (tid >> 2);
        int part = tid & 3;
        float s = 0.f;
        int wbase = b * (HID / 2) + part * 64;
        const float* wd = W_dec + part * 128;
#pragma unroll 8
        for (int w = 0; w < 64; ++w) {
            uint32_t uh = hh[wbase + w], ul = hl[wbase + w];
            __nv_bfloat162 vh = *reinterpret_cast<__nv_bfloat162*>(&uh);
            __nv_bfloat162 vl = *reinterpret_cast<__nv_bfloat162*>(&ul);
            float e0 = __bfloat162float(__low2bfloat16(vh))  + __bfloat162float(__low2bfloat16(vl));
            float e1 = __bfloat162float(__high2bfloat16(vh)) + __bfloat162float(__high2bfloat16(vl));
            s = fmaf(e0, wd[2 * w], s);
            s = fmaf(e1, wd[2 * w + 1], s);
        }
        s += __shfl_down_sync(0xFFFFFFFF, s, 2, 4);
        s += __shfl_down_sync(0xFFFFFFFF, s, 1, 4);
        if (part == 0) out[b] = s + b_dec[0];
    }
#undef GROUP_BARRIER
}

extern "C" void kernel_launch(void* const* d_in, const int* in_sizes, int n_in,
                              void* d_out, int out_size)
{
    (void)in_sizes; (void)n_in; (void)out_size;
    const float* x     = (const float*)d_in[0];
    const float* h0    = (const float*)d_in[1];
    const float* c0    = (const float*)d_in[2];
    const float* W_ih  = (const float*)d_in[3];
    const float* W_hh  = (const float*)d_in[4];
    const float* b_ih  = (const float*)d_in[5];
    const float* b_hh  = (const float*)d_in[6];
    const float* W_dec = (const float*)d_in[7];
    const float* b_dec = (const float*)d_in[8];
    float* out = (float*)d_out;

    static bool attr_set = false;
    if (!attr_set) {
        cudaFuncSetAttribute(lstm_all_kernel,
                             cudaFuncAttributeMaxDynamicSharedMemorySize, SMEM_BYTES);
        attr_set = true;
    }

    dim3 grid(HID / JT, BATCH / BT);   // (32, 4) = 128 blocks, all co-resident
    lstm_all_kernel<<<grid, 256, SMEM_BYTES>>>(x, h0, c0, W_ih, W_hh,
                                               b_ih, b_hh, W_dec, b_dec, out);
}

// round 12
// speedup vs baseline: 2.0280x; 1.3974x over previous
#include <cuda_runtime.h>
#include <cuda_fp16.h>
#include <math.h>
#include <stdint.h>

// Problem dims (fixed)
#define T_STEPS 2048
#define BATCH   256
#define INP     256
#define HID     512
#define KTOT    768

// Block = (jTile 0..31, bTile 0..3): 16 hidden cols x 64 batch rows; 128 blocks
#define JT 16
#define BT 64
#define KC 64                  // k elems per staged chunk
#define NCH (KTOT / KC)        // 12 chunks (0-3: x, 4-11: h)
#define NBG 32                 // blocks per barrier group (one bTile)

// SMEM strides in 32-bit words (stride % 32 == 4 -> conflict-free ldmatrix rows)
#define W_STRIDE 388           // 768 fp16 = 384 words + 4 pad
#define A_STRIDE 36            // 64 fp16  = 32 words + 4 pad
#define G_STRIDE 65
#define ABUF_WORDS (BT * A_STRIDE)     // 2304
#define ABUF_BYTES (ABUF_WORDS * 4)    // 9216

#define SZ_W      (64 * W_STRIDE * 4)  // 99,328 per plane
#define OFF_WHI   0
#define OFF_WLO   SZ_W                 // 99,328
#define OFF_ABUF  (2 * SZ_W)           // 198,656 (2 bufs x 9216 = 18,432)
#define OFF_GATES OFF_ABUF             // overlay: 64*65*4 = 16,640 <= 18,432
#define OFF_BIAS  (OFF_ABUF + 2 * ABUF_BYTES)   // 217,088
#define SMEM_BYTES (OFF_BIAS + 256 + 16)        // 217,360

// Persistent state: h as packed half2 words, double-buffered; fp32 copy for decode
__device__ uint32_t g_h[2][BATCH * HID / 2];
__device__ float    g_hf[BATCH * HID];
__device__ volatile int g_sense4[4];
__device__ int          g_count4[4];

__device__ __forceinline__ uint32_t h2u(__half2 v) {
    return *reinterpret_cast<uint32_t*>(&v);
}
__device__ __forceinline__ float fast_sigmoid(float x) {
    x = fminf(fmaxf(x, -30.f), 30.f);
    return __fdividef(1.f, 1.f + __expf(-x));
}
__device__ __forceinline__ float fast_tanh(float x) {
    x = fminf(fmaxf(x, -15.f), 15.f);
    float e = __expf(2.f * x);
    return __fdividef(e - 1.f, e + 1.f);
}
__device__ __forceinline__ void ldsm4(uint32_t* r, uint32_t saddr) {
    asm volatile("ldmatrix.sync.aligned.m8n8.x4.shared.b16 {%0,%1,%2,%3}, [%4];"
                 : "=r"(r[0]), "=r"(r[1]), "=r"(r[2]), "=r"(r[3]) : "r"(saddr));
}
#define MMA_F16(D, A, B0, B1)                                               \
    asm volatile("mma.sync.aligned.m16n8k16.row.col.f32.f16.f16.f32 "       \
                 "{%0,%1,%2,%3}, {%4,%5,%6,%7}, {%8,%9}, {%0,%1,%2,%3};"    \
                 : "+f"((D)[0]), "+f"((D)[1]), "+f"((D)[2]), "+f"((D)[3])   \
                 : "r"((A)[0]), "r"((A)[1]), "r"((A)[2]), "r"((A)[3]),      \
                   "r"(B0), "r"(B1));

// ONE kernel: init + 2048 fused steps + decode. Grid (32, 4) x 256 threads.
__global__ __launch_bounds__(256, 1)
void lstm_fp16_kernel(const float* __restrict__ x_all,
                      const float* __restrict__ h0,
                      const float* __restrict__ c0,
                      const float* __restrict__ W_ih,
                      const float* __restrict__ W_hh,
                      const float* __restrict__ b_ih,
                      const float* __restrict__ b_hh,
                      const float* __restrict__ W_dec,
                      const float* __restrict__ b_dec,
                      float* __restrict__ out)
{
    extern __shared__ __align__(16) char sm[];
    uint32_t* Whi    = (uint32_t*)(sm + OFF_WHI);
    uint32_t* Wlo    = (uint32_t*)(sm + OFF_WLO);
    uint32_t* Ab     = (uint32_t*)(sm + OFF_ABUF);
    float*    gates  = (float*)   (sm + OFF_GATES);   // overlay on Ab
    float*    bias_s = (float*)   (sm + OFF_BIAS);

    const int tid  = threadIdx.x;
    const int lane = tid & 31, warp = tid >> 5;
    const int wm = warp & 1;        // batch half (32 rows)
    const int wn = warp >> 1;       // 16-gatecol slice (0..3)
    const int jTile = blockIdx.x;   // 0..31
    const int bTile = blockIdx.y;   // 0..3 (= barrier group)

    // ---- one-time: weights -> SMEM, fp16 hi + lo planes (K-major, padded) ----
    {
        int r = tid >> 2;                        // weight row 0..63 (tt*16+jj)
        int grow = (r >> 4) * HID + jTile * JT + (r & 15);
        int kbase = (tid & 3) * 192;
        for (int i = 0; i < 96; ++i) {
            int k = kbase + 2 * i;
            float2 v = (k < INP)
                ? *(const float2*)(W_ih + (size_t)grow * INP + k)
                : *(const float2*)(W_hh + (size_t)grow * HID + (k - INP));
            __half hx = __float2half_rn(v.x), hy = __float2half_rn(v.y);
            __half lx = __float2half_rn(v.x - __half2float(hx));
            __half ly = __float2half_rn(v.y - __half2float(hy));
            Whi[r * W_STRIDE + k / 2] = h2u(__halves2half2(hx, hy));
            Wlo[r * W_STRIDE + k / 2] = h2u(__halves2half2(lx, ly));
        }
        if (tid < 64) {
            int gr = (tid >> 4) * HID + jTile * JT + (tid & 15);
            bias_s[tid] = b_ih[gr] + b_hh[gr];
        }
    }

    // ---- epilogue ownership: thread owns (eb, ej0..ej0+3); c in registers ----
    const int eb  = tid >> 2;
    const int ebg = bTile * BT + eb;
    const int ej0 = (tid & 3) * 4;
    const int jg0 = jTile * JT + ej0;
    const int hwi = ebg * (HID / 2) + jg0 / 2;   // half2-word index
    float creg[4];
    {
        float4 cv = *(const float4*)(c0 + (size_t)ebg * HID + jg0);
        creg[0] = cv.x; creg[1] = cv.y; creg[2] = cv.z; creg[3] = cv.w;
        float4 hv = *(const float4*)(h0 + (size_t)ebg * HID + jg0);
        *(uint2*)&g_h[0][hwi] = make_uint2(h2u(__floats2half2_rn(hv.x, hv.y)),
                                           h2u(__floats2half2_rn(hv.z, hv.w)));
    }

    int my_sense = g_sense4[bTile];
#define GROUP_BARRIER()                                                     \
    do {                                                                    \
        __syncthreads();                                                    \
        if (tid == 0) {                                                     \
            my_sense ^= 1;                                                  \
            __threadfence();                                                \
            if (atomicAdd(&g_count4[bTile], 1) == NBG - 1) {                \
                g_count4[bTile] = 0;                                        \
                __threadfence();                                            \
                g_sense4[bTile] = my_sense;                                 \
            } else {                                                        \
                while (g_sense4[bTile] != my_sense) { }                     \
                __threadfence();                                            \
            }                                                               \
        }                                                                   \
        __syncthreads();                                                    \
    } while (0)

    GROUP_BARRIER();   // publish h init

    // ---- ldmatrix lane addressing (bytes, shared space) ----
    const uint32_t ab_sh  = (uint32_t)__cvta_generic_to_shared(Ab);
    const uint32_t whi_sh = (uint32_t)__cvta_generic_to_shared(Whi);
    const uint32_t wlo_sh = (uint32_t)__cvta_generic_to_shared(Wlo);
    const int rowoff = (lane & 7) + ((lane >> 3) & 1) * 8;
    const int khalf4 = (lane >> 4) * 4;          // word offset for k-half
    const uint32_t wlane_hi = whi_sh + ((wn * 16 + rowoff) * W_STRIDE + khalf4) * 4;
    const uint32_t wlane_lo = wlo_sh + ((wn * 16 + rowoff) * W_STRIDE + khalf4) * 4;
    uint32_t alane[2];
#pragma unroll
    for (int mf = 0; mf < 2; ++mf)
        alane[mf] = ab_sh + ((wm * 32 + mf * 16 + rowoff) * A_STRIDE + khalf4) * 4;

    // staging: 4 threads per batch row, 16 k elems (8 half2 words) each
    const int srow = tid >> 2;
    const int sq   = tid & 3;
    const int sbrow = bTile * BT + srow;
    const int sdst  = srow * A_STRIDE + sq * 8;  // word offset in A plane

    for (int t = 0; t < T_STEPS; ++t) {
        const float* __restrict__ x_t = x_all + (size_t)t * BATCH * INP;
        const uint32_t* __restrict__ h_in = g_h[t & 1];
        uint32_t* __restrict__ h_out = g_h[(t & 1) ^ 1];

        float d[2][2][4];
#pragma unroll
        for (int mf = 0; mf < 2; ++mf)
#pragma unroll
            for (int nf = 0; nf < 2; ++nf)
#pragma unroll
                for (int q = 0; q < 4; ++q) d[mf][nf][q] = 0.f;

        // ---- stage chunk 0 (pure x) into buf 0 ----
        {
            const float* src = x_t + (size_t)sbrow * INP + sq * 16;
            float4 f0 = *(const float4*)(src);
            float4 f1 = *(const float4*)(src + 4);
            float4 f2 = *(const float4*)(src + 8);
            float4 f3 = *(const float4*)(src + 12);
            uint4 pa = make_uint4(h2u(__floats2half2_rn(f0.x, f0.y)),
                                  h2u(__floats2half2_rn(f0.z, f0.w)),
                                  h2u(__floats2half2_rn(f1.x, f1.y)),
                                  h2u(__floats2half2_rn(f1.z, f1.w)));
            uint4 pb = make_uint4(h2u(__floats2half2_rn(f2.x, f2.y)),
                                  h2u(__floats2half2_rn(f2.z, f2.w)),
                                  h2u(__floats2half2_rn(f3.x, f3.y)),
                                  h2u(__floats2half2_rn(f3.z, f3.w)));
            *(uint4*)&Ab[sdst]     = pa;
            *(uint4*)&Ab[sdst + 4] = pb;
        }
        __syncthreads();

        int buf = 0;
        for (int c = 0; c < NCH; ++c) {
            // ---- prefetch chunk c+1 ----
            uint4 pa, pb;
            bool have_next = (c < NCH - 1);
            if (have_next) {
                int cn = c + 1;
                if (cn < 4) {   // x chunk: LDG fp32 + cvt
                    const float* src = x_t + (size_t)sbrow * INP + cn * KC + sq * 16;
                    float4 f0 = *(const float4*)(src);
                    float4 f1 = *(const float4*)(src + 4);
                    float4 f2 = *(const float4*)(src + 8);
                    float4 f3 = *(const float4*)(src + 12);
                    pa = make_uint4(h2u(__floats2half2_rn(f0.x, f0.y)),
                                    h2u(__floats2half2_rn(f0.z, f0.w)),
                                    h2u(__floats2half2_rn(f1.x, f1.y)),
                                    h2u(__floats2half2_rn(f1.z, f1.w)));
                    pb = make_uint4(h2u(__floats2half2_rn(f2.x, f2.y)),
                                    h2u(__floats2half2_rn(f2.z, f2.w)),
                                    h2u(__floats2half2_rn(f3.x, f3.y)),
                                    h2u(__floats2half2_rn(f3.z, f3.w)));
                } else {        // h chunk: already fp16 words
                    int widx = sbrow * (HID / 2) + (cn - 4) * 32 + sq * 8;
                    pa = *(const uint4*)&h_in[widx];
                    pb = *(const uint4*)&h_in[widx + 4];
                }
            }

            // ---- MMAs on chunk c: 4 k16-slices x (2 mf x 2 nf x 2 planes) ----
            const uint32_t aoff = (uint32_t)(buf * ABUF_BYTES);
#pragma unroll
            for (int ks = 0; ks < 4; ++ks) {
                const uint32_t s32 = (uint32_t)((c * 4 + ks) * 32);
                uint32_t bh[4], bl[4];
                ldsm4(bh, wlane_hi + s32);
                ldsm4(bl, wlane_lo + s32);
#pragma unroll
                for (int mf = 0; mf < 2; ++mf) {
                    uint32_t a[4];
                    ldsm4(a, alane[mf] + aoff + (uint32_t)(ks * 32));
                    MMA_F16(d[mf][0], a, bh[0], bh[2]);
                    MMA_F16(d[mf][1], a, bh[1], bh[3]);
                    MMA_F16(d[mf][0], a, bl[0], bl[2]);
                    MMA_F16(d[mf][1], a, bl[1], bl[3]);
                }
            }

            // ---- commit prefetched chunk ----
            if (have_next) {
                int nb = buf ^ 1;
                *(uint4*)&Ab[nb * ABUF_WORDS + sdst]     = pa;
                *(uint4*)&Ab[nb * ABUF_WORDS + sdst + 4] = pb;
            }
            __syncthreads();
            buf ^= 1;
        }

        // ---- spill accumulators to gates buffer (overlays A bufs) ----
        {
            const int lq = lane >> 2, lr4 = lane & 3;
#pragma unroll
            for (int mf = 0; mf < 2; ++mf)
#pragma unroll
                for (int nf = 0; nf < 2; ++nf) {
                    int m = wm * 32 + mf * 16 + lq;
                    int n = wn * 16 + nf * 8 + lr4 * 2;
                    gates[ m      * G_STRIDE + n    ] = d[mf][nf][0];
                    gates[ m      * G_STRIDE + n + 1] = d[mf][nf][1];
                    gates[(m + 8) * G_STRIDE + n    ] = d[mf][nf][2];
                    gates[(m + 8) * G_STRIDE + n + 1] = d[mf][nf][3];
                }
        }
        __syncthreads();

        // ---- LSTM epilogue: c in regs, h stored fp16 (fp32 copy on last step) ----
        {
            float hnew[4];
#pragma unroll
            for (int i = 0; i < 4; ++i) {
                int j = ej0 + i;
                float gi = gates[eb * G_STRIDE + j]      + bias_s[j];
                float gf = gates[eb * G_STRIDE + 16 + j] + bias_s[16 + j];
                float gg = gates[eb * G_STRIDE + 32 + j] + bias_s[32 + j];
                float go = gates[eb * G_STRIDE + 48 + j] + bias_s[48 + j];
                float iv = fast_sigmoid(gi);
                float fv = fast_sigmoid(gf);
                float gv = fast_tanh(gg);
                float ov = fast_sigmoid(go);
                float cn = fv * creg[i] + iv * gv;
                creg[i] = cn;
                hnew[i] = ov * fast_tanh(cn);
            }
            *(uint2*)&h_out[hwi] =
                make_uint2(h2u(__floats2half2_rn(hnew[0], hnew[1])),
                           h2u(__floats2half2_rn(hnew[2], hnew[3])));
            if (t == T_STEPS - 1)
                *(float4*)&g_hf[(size_t)ebg * HID + jg0] =
                    make_float4(hnew[0], hnew[1], hnew[2], hnew[3]);
        }

        GROUP_BARRIER();   // publish h to this bTile group
    }

    // ---- decode by jTile==0 blocks from the fp32 h copy ----
    if (jTile == 0) {
        int b = bTile * BT + (tid >> 2);
        int part = tid & 3;
        const float* hb = g_hf + (size_t)b * HID + part * 128;
        const float* wd = W_dec + part * 128;
        float s = 0.f;
#pragma unroll 8
        for (int i = 0; i < 128; ++i) s = fmaf(hb[i], wd[i], s);
        s += __shfl_down_sync(0xFFFFFFFF, s, 2, 4);
        s += __shfl_down_sync(0xFFFFFFFF, s, 1, 4);
        if (part == 0) out[b] = s + b_dec[0];
    }
#undef GROUP_BARRIER
}

extern "C" void kernel_launch(void* const* d_in, const int* in_sizes, int n_in,
                              void* d_out, int out_size)
{
    (void)in_sizes; (void)n_in; (void)out_size;
    const float* x     = (const float*)d_in[0];
    const float* h0    = (const float*)d_in[1];
    const float* c0    = (const float*)d_in[2];
    const float* W_ih  = (const float*)d_in[3];
    const float* W_hh  = (const float*)d_in[4];
    const float* b_ih  = (const float*)d_in[5];
    const float* b_hh  = (const float*)d_in[6];
    const float* W_dec = (const float*)d_in[7];
    const float* b_dec = (const float*)d_in[8];
    float* out = (float*)d_out;

    static bool attr_set = false;
    if (!attr_set) {
        cudaFuncSetAttribute(lstm_fp16_kernel,
                             cudaFuncAttributeMaxDynamicSharedMemorySize, SMEM_BYTES);
        attr_set = true;
    }

    dim3 grid(HID / JT, BATCH / BT);   // (32, 4) = 128 blocks, all co-resident
    lstm_fp16_kernel<<<grid, 256, SMEM_BYTES>>>(x, h0, c0, W_ih, W_hh,
                                                b_ih, b_hh, W_dec, b_dec, out);
}